// round 13
// baseline (speedup 1.0000x reference)
#include <cuda_runtime.h>
#include <cuda_fp16.h>
#include <cstdint>

// Problem constants
#define BATCH 512
#define SEQ   256
#define CEMB  384
#define HEAD  64
#define SCALE 0.125f
#define QKV_N 192
#define KC    32
#define NKCHUNK 12

// Device-global scratch (allowed)
__device__ __half g_QK[(size_t)BATCH * SEQ * 128];   // [m][128] : Q(scaled)|K, fp16
__device__ __half g_VT[(size_t)BATCH * HEAD * SEQ];  // [b][h][s] : V transposed, fp16
__device__ __half g_WB[(size_t)QKV_N * CEMB];        // [n][k] fused weights, fp16
__device__ float  g_bias[QKV_N];                     // fused bias (Q part pre-scaled)

// ---------------------------------------------------------------------------
// helpers
// ---------------------------------------------------------------------------
__device__ __forceinline__ uint32_t sptr(const void* p) {
    uint32_t a;
    asm("{ .reg .u64 t; cvta.to.shared.u64 t, %1; cvt.u32.u64 %0, t; }"
        : "=r"(a) : "l"(p));
    return a;
}
__device__ __forceinline__ uint32_t packh2(float x, float y) {
    __half2 h = __floats2half2_rn(x, y);
    return *(uint32_t*)&h;
}
#define LDM_X4(r, addr)                                                         \
    asm volatile("ldmatrix.sync.aligned.m8n8.x4.shared.b16 {%0,%1,%2,%3}, [%4];" \
        : "=r"((r)[0]), "=r"((r)[1]), "=r"((r)[2]), "=r"((r)[3]) : "r"(addr))
#define LDM_X2(r, addr)                                                         \
    asm volatile("ldmatrix.sync.aligned.m8n8.x2.shared.b16 {%0,%1}, [%2];"      \
        : "=r"((r)[0]), "=r"((r)[1]) : "r"(addr))

// m16n8k16 fp16 HMMA, f32 accumulate (sm_80+ portable path)
__device__ __forceinline__ void mma_f16(float* d, const uint32_t* a, const uint32_t* b) {
    asm volatile("mma.sync.aligned.m16n8k16.row.col.f32.f16.f16.f32 "
        "{%0,%1,%2,%3}, {%4,%5,%6,%7}, {%8,%9}, {%0,%1,%2,%3};"
        : "+f"(d[0]), "+f"(d[1]), "+f"(d[2]), "+f"(d[3])
        : "r"(a[0]), "r"(a[1]), "r"(a[2]), "r"(a[3]), "r"(b[0]), "r"(b[1]));
}

// ---------------------------------------------------------------------------
// Prep: Wq|Wk|Wv -> g_WB [n=192][k=384] fp16 (Q part pre-scaled by SCALE)
// ---------------------------------------------------------------------------
__global__ void prep_kernel(const float* __restrict__ Wq, const float* __restrict__ bq,
                            const float* __restrict__ Wk, const float* __restrict__ bk,
                            const float* __restrict__ Wv, const float* __restrict__ bv) {
    int i = blockIdx.x * 256 + threadIdx.x;
    if (i < QKV_N * CEMB) {
        int n = i / CEMB, k = i % CEMB;
        const float* W = (n < 64) ? Wq : (n < 128) ? Wk : Wv;
        float w = W[(size_t)k * HEAD + (n & 63)];
        if (n < 64) w *= SCALE;
        g_WB[i] = __float2half(w);
    }
    if (i < QKV_N) {
        const float* bb = (i < 64) ? bq : (i < 128) ? bk : bv;
        float v = bb[i & 63];
        if (i < 64) v *= SCALE;
        g_bias[i] = v;
    }
}

// ---------------------------------------------------------------------------
// Kernel 1: fused QKV projection, fp16 m16n8k16, full N=192 per CTA.
//   grid = 1024 (m-tiles of 128), 512 threads (16 warps, 4x4 grid).
//   Warp tile 32x48 = 2x6 atoms. KC=32 (2 k-steps of 16).
//   Double-buffered SMEM (one sync per chunk) + register prefetch.
//   Epilogue: cols<128 -> g_QK fp16 rows; cols>=128 -> g_VT transposed fp16.
// SMEM halves: sA[2][128*40] | sB[2][192*40] ; then bias f32[192]
// ---------------------------------------------------------------------------
#define QSTR 40                 // row stride in halves (80 B; conflict-free ldmatrix)
#define SA_HALVES (128 * QSTR)  // 5120
#define SB_HALVES (192 * QSTR)  // 7680
#define QKV_SMEM_BYTES ((2 * SA_HALVES + 2 * SB_HALVES) * 2 + QKV_N * 4)

__global__ __launch_bounds__(512)
void qkv_hmma_kernel(const float* __restrict__ x) {
    extern __shared__ __half smh[];
    __half* sA = smh;                               // [2][128][40]
    __half* sB = smh + 2 * SA_HALVES;               // [2][192][40]
    float* sbias = (float*)(smh + 2 * SA_HALVES + 2 * SB_HALVES);

    const int tid  = threadIdx.x;
    const int lane = tid & 31;
    const int wid  = tid >> 5;
    const int gid  = lane >> 2;
    const int tig  = lane & 3;
    const int m0   = blockIdx.x * 128;
    const int wm   = (wid >> 2) * 32;      // 0,32,64,96
    const int wn   = (wid & 3) * 48;       // 0,48,96,144

    if (tid < QKV_N) sbias[tid] = g_bias[tid];

    float acc[2][6][4];
    #pragma unroll
    for (int ma = 0; ma < 2; ++ma)
        #pragma unroll
        for (int na = 0; na < 6; ++na)
            #pragma unroll
            for (int j = 0; j < 4; ++j) acc[ma][na][j] = 0.f;

    // per-thread load slots
    const int arow = tid >> 3, ak4 = (tid & 7) * 4;   // A rows arow, arow+64
    const int bn0  = tid >> 2, bs0 = (tid & 3) * 8;   // B row 0..127
    const int bn1  = 128 + (tid >> 2);                // B row 128..191 (tid<256)
    float4 pa[2];
    uint4  pb0, pb1;

    // prefetch chunk 0
    pa[0] = *(const float4*)(x + (size_t)(m0 + arow) * CEMB + ak4);
    pa[1] = *(const float4*)(x + (size_t)(m0 + arow + 64) * CEMB + ak4);
    pb0 = *(const uint4*)(g_WB + (size_t)bn0 * CEMB + bs0);
    if (tid < 256) pb1 = *(const uint4*)(g_WB + (size_t)bn1 * CEMB + bs0);

    for (int c = 0; c < NKCHUNK; ++c) {
        const int buf = c & 1;
        __half* sAb = sA + buf * SA_HALVES;
        __half* sBb = sB + buf * SB_HALVES;

        // store prefetched chunk (f32 -> fp16 for A)
        #pragma unroll
        for (int it = 0; it < 2; ++it) {
            uint2 s;
            s.x = packh2(pa[it].x, pa[it].y);
            s.y = packh2(pa[it].z, pa[it].w);
            *(uint2*)&sAb[(arow + it * 64) * QSTR + ak4] = s;
        }
        *(uint4*)&sBb[bn0 * QSTR + bs0] = pb0;
        if (tid < 256) *(uint4*)&sBb[bn1 * QSTR + bs0] = pb1;
        __syncthreads();

        // prefetch next chunk (overlaps with compute below)
        if (c + 1 < NKCHUNK) {
            const int kb = (c + 1) * KC;
            pa[0] = *(const float4*)(x + (size_t)(m0 + arow) * CEMB + kb + ak4);
            pa[1] = *(const float4*)(x + (size_t)(m0 + arow + 64) * CEMB + kb + ak4);
            pb0 = *(const uint4*)(g_WB + (size_t)bn0 * CEMB + kb + bs0);
            if (tid < 256) pb1 = *(const uint4*)(g_WB + (size_t)bn1 * CEMB + kb + bs0);
        }

        // compute: 2 k-steps of 16
        #pragma unroll
        for (int ks = 0; ks < 2; ++ks) {
            const int k0 = ks * 16;
            uint32_t a[2][4];
            #pragma unroll
            for (int ma = 0; ma < 2; ++ma) {
                uint32_t ad = sptr(&sAb[(wm + ma * 16 + (lane & 15)) * QSTR
                                        + k0 + ((lane >> 4) & 1) * 8]);
                LDM_X4(a[ma], ad);
            }
            #pragma unroll
            for (int na = 0; na < 6; ++na) {
                uint32_t b2[2];
                uint32_t bd = sptr(&sBb[(wn + na * 8 + (lane & 7)) * QSTR
                                        + k0 + ((lane >> 3) & 1) * 8]);
                LDM_X2(b2, bd);
                mma_f16(acc[0][na], a[0], b2);
                mma_f16(acc[1][na], a[1], b2);
            }
        }
        // no second sync: next store targets the other buffer; the sync above
        // (next iteration) orders compute(c) before store(c+2) to this buffer.
    }

    // Epilogue: bias; cols<128 -> g_QK, cols>=128 -> g_VT (transposed)
    #pragma unroll
    for (int ma = 0; ma < 2; ++ma) {
        int r  = m0 + wm + ma * 16 + gid;
        int bb = r >> 8;
        int sq = r & 255;
        #pragma unroll
        for (int na = 0; na < 6; ++na) {
            int cg = wn + na * 8 + 2 * tig;    // global col 0..191
            float v0 = acc[ma][na][0] + sbias[cg];
            float v1 = acc[ma][na][1] + sbias[cg + 1];
            float v2 = acc[ma][na][2] + sbias[cg];
            float v3 = acc[ma][na][3] + sbias[cg + 1];
            if (cg < 128) {   // uniform per (warp,na): 8-col atom never straddles 128
                *(__half2*)(g_QK + (size_t)r * 128 + cg)       = __floats2half2_rn(v0, v1);
                *(__half2*)(g_QK + (size_t)(r + 8) * 128 + cg) = __floats2half2_rn(v2, v3);
            } else {
                __half* vt = g_VT + ((size_t)bb * HEAD + (cg - 128)) * SEQ + sq;
                vt[0]       = __float2half(v0);   // (h,   sq)
                vt[SEQ]     = __float2half(v1);   // (h+1, sq)
                vt[8]       = __float2half(v2);   // (h,   sq+8)
                vt[SEQ + 8] = __float2half(v3);   // (h+1, sq+8)
            }
        }
    }
}

// ---------------------------------------------------------------------------
// Kernel 2: causal attention, fp16 m16n8k16.  grid (4, 512), 256 threads.
//   (unchanged from R11 passing version)
// ---------------------------------------------------------------------------
#define SS_STR 264
#define ATTN_SMEM_BYTES ((64 * SS_STR + 576) * 4 + (64 * 72) * 2 * 2)

__global__ __launch_bounds__(256)
void attn_kernel(float* __restrict__ outp) {
    extern __shared__ float sm[];
    float* sS    = sm;                        // [64][264] f32 scores/probs
    float* redm  = sS + 64 * SS_STR;
    float* reds  = redm + 256;
    float* rsum  = reds + 256;
    __half* sQ   = (__half*)(rsum + 64);      // [64][72]
    __half* sKV  = sQ + 64 * 72;              // [64][72]  K[s][h] / V^T[h][s]

    const int tid  = threadIdx.x;
    const int lane = tid & 31;
    const int wid  = tid >> 5;
    const int gid  = lane >> 2;
    const int tig  = lane & 3;
    const int wm   = (wid >> 1) * 16;
    const int wn   = (wid & 1) * 32;
    const int b    = blockIdx.y;
    const int qt   = blockIdx.x;
    const int r0   = qt * 64;

    // Load Q tile (fp16, pre-scaled): [q][h], 512 uint4
    {
        const __half* Qg = g_QK + ((size_t)b * SEQ + r0) * 128;
        #pragma unroll
        for (int it = 0; it < 2; ++it) {
            int idx = tid + it * 256;
            int q = idx >> 3, seg = (idx & 7) * 8;
            *(uint4*)&sQ[q * 72 + seg] = *(const uint4*)(Qg + (size_t)q * 128 + seg);
        }
    }

    // ---------------- Phase 1: S = Q K^T ----------------
    for (int kt = 0; kt <= qt; ++kt) {
        const __half* Kg = g_QK + ((size_t)b * SEQ + kt * 64) * 128 + 64;
        #pragma unroll
        for (int it = 0; it < 2; ++it) {
            int idx = tid + it * 256;
            int s = idx >> 3, seg = (idx & 7) * 8;
            *(uint4*)&sKV[s * 72 + seg] = *(const uint4*)(Kg + (size_t)s * 128 + seg);
        }
        __syncthreads();

        float accS[4][4];
        #pragma unroll
        for (int na = 0; na < 4; ++na)
            #pragma unroll
            for (int j = 0; j < 4; ++j) accS[na][j] = 0.f;

        #pragma unroll
        for (int ks = 0; ks < 4; ++ks) {
            const int k0 = ks * 16;
            uint32_t a[4];
            uint32_t ad = sptr(&sQ[(wm + (lane & 15)) * 72 + k0 + ((lane >> 4) & 1) * 8]);
            LDM_X4(a, ad);
            #pragma unroll
            for (int na = 0; na < 4; ++na) {
                uint32_t b2[2];
                uint32_t bd = sptr(&sKV[(wn + na * 8 + (lane & 7)) * 72
                                        + k0 + ((lane >> 3) & 1) * 8]);
                LDM_X2(b2, bd);
                mma_f16(accS[na], a, b2);
            }
        }

        // store S with causal mask on diagonal tile
        #pragma unroll
        for (int na = 0; na < 4; ++na) {
            int q0 = wm + gid;
            int cl = wn + na * 8 + 2 * tig;
            float2 v0 = make_float2(accS[na][0], accS[na][1]);
            float2 v1 = make_float2(accS[na][2], accS[na][3]);
            if (kt == qt) {
                if (cl     > q0)     v0.x = -1e30f;
                if (cl + 1 > q0)     v0.y = -1e30f;
                if (cl     > q0 + 8) v1.x = -1e30f;
                if (cl + 1 > q0 + 8) v1.y = -1e30f;
            }
            *(float2*)(&sS[q0 * SS_STR + kt * 64 + cl])       = v0;
            *(float2*)(&sS[(q0 + 8) * SS_STR + kt * 64 + cl]) = v1;
        }
        __syncthreads();
    }

    // ---------------- Softmax (f32, unnormalized exp + row sums) ----------------
    const int nk = (qt + 1) * 64;
    {
        int r = tid >> 2;
        int p = tid & 3;
        int chunk = nk >> 2;
        float* row = sS + r * SS_STR + p * chunk;
        float m = -3.4e38f;
        for (int t = 0; t < chunk; ++t) m = fmaxf(m, row[t]);
        redm[r * 4 + p] = m;
        __syncthreads();
        float mm = fmaxf(fmaxf(redm[r * 4], redm[r * 4 + 1]),
                         fmaxf(redm[r * 4 + 2], redm[r * 4 + 3]));
        float s = 0.f;
        for (int t = 0; t < chunk; ++t) {
            float e = __expf(row[t] - mm);
            row[t] = e;
            s += e;
        }
        reds[r * 4 + p] = s;
        __syncthreads();
        if (p == 0)
            rsum[r] = reds[r * 4] + reds[r * 4 + 1] + reds[r * 4 + 2] + reds[r * 4 + 3];
        __syncthreads();
    }

    // ---------------- Phase 2: O = P V ----------------
    float accO[4][4];
    #pragma unroll
    for (int na = 0; na < 4; ++na)
        #pragma unroll
        for (int j = 0; j < 4; ++j) accO[na][j] = 0.f;

    const __half* VTg = g_VT + (size_t)b * HEAD * SEQ;
    for (int kt = 0; kt <= qt; ++kt) {
        // V^T tile: sKV[h][s], coalesced, conflict-free
        #pragma unroll
        for (int it = 0; it < 2; ++it) {
            int idx = tid + it * 256;
            int h = idx >> 3, seg = (idx & 7) * 8;
            *(uint4*)&sKV[h * 72 + seg] = *(const uint4*)(VTg + (size_t)h * SEQ + kt * 64 + seg);
        }
        __syncthreads();

        #pragma unroll
        for (int ks = 0; ks < 4; ++ks) {
            const int k0 = kt * 64 + ks * 16;
            const float* pr0 = &sS[(wm + gid) * SS_STR + k0];
            const float* pr8 = pr0 + 8 * SS_STR;
            float2 f0 = *(const float2*)(pr0 + 2 * tig);
            float2 f1 = *(const float2*)(pr8 + 2 * tig);
            float2 f2 = *(const float2*)(pr0 + 8 + 2 * tig);
            float2 f3 = *(const float2*)(pr8 + 8 + 2 * tig);
            uint32_t a[4] = { packh2(f0.x, f0.y), packh2(f1.x, f1.y),
                              packh2(f2.x, f2.y), packh2(f3.x, f3.y) };
            #pragma unroll
            for (int na = 0; na < 4; ++na) {
                uint32_t b2[2];
                uint32_t bd = sptr(&sKV[(wn + na * 8 + (lane & 7)) * 72
                                        + ks * 16 + ((lane >> 3) & 1) * 8]);
                LDM_X2(b2, bd);
                mma_f16(accO[na], a, b2);
            }
        }
        __syncthreads();
    }

    // Epilogue: normalize, store f32
    {
        float inv0 = 1.0f / rsum[wm + gid];
        float inv1 = 1.0f / rsum[wm + gid + 8];
        #pragma unroll
        for (int na = 0; na < 4; ++na) {
            int c = wn + na * 8 + 2 * tig;
            float2 o0 = make_float2(accO[na][0] * inv0, accO[na][1] * inv0);
            float2 o1 = make_float2(accO[na][2] * inv1, accO[na][3] * inv1);
            *(float2*)(outp + ((size_t)b * SEQ + r0 + wm + gid) * HEAD + c)      = o0;
            *(float2*)(outp + ((size_t)b * SEQ + r0 + wm + gid + 8) * HEAD + c)  = o1;
        }
    }
}

// ---------------------------------------------------------------------------
extern "C" void kernel_launch(void* const* d_in, const int* in_sizes, int n_in,
                              void* d_out, int out_size) {
    const float* x  = (const float*)d_in[0];
    const float* Wq = (const float*)d_in[1];
    const float* bq = (const float*)d_in[2];
    const float* Wk = (const float*)d_in[3];
    const float* bk = (const float*)d_in[4];
    const float* Wv = (const float*)d_in[5];
    const float* bv = (const float*)d_in[6];
    float* out = (float*)d_out;

    prep_kernel<<<(QKV_N * CEMB + 255) / 256, 256>>>(Wq, bq, Wk, bk, Wv, bv);

    cudaFuncSetAttribute(qkv_hmma_kernel, cudaFuncAttributeMaxDynamicSharedMemorySize,
                         QKV_SMEM_BYTES);
    qkv_hmma_kernel<<<(BATCH * SEQ) / 128, 512, QKV_SMEM_BYTES>>>(x);

    cudaFuncSetAttribute(attn_kernel, cudaFuncAttributeMaxDynamicSharedMemorySize,
                         ATTN_SMEM_BYTES);
    attn_kernel<<<dim3(4, BATCH), 256, ATTN_SMEM_BYTES>>>(out);
}

// round 14
// speedup vs baseline: 1.2774x; 1.2774x over previous
#include <cuda_runtime.h>
#include <cuda_fp16.h>
#include <cstdint>

// Problem constants
#define BATCH 512
#define SEQ   256
#define CEMB  384
#define HEAD  64
#define SCALE 0.125f
#define QKV_N 192
#define KC    32
#define NKCHUNK 12

// Device-global scratch (allowed)
__device__ __half g_QK[(size_t)BATCH * SEQ * 128];   // [m][128] : Q(scaled)|K, fp16
__device__ __half g_VT[(size_t)BATCH * HEAD * SEQ];  // [b][h][s] : V transposed, fp16
__device__ __half g_WB[(size_t)QKV_N * CEMB];        // [n][k] fused weights, fp16
__device__ float  g_bias[QKV_N];                     // fused bias (Q part pre-scaled)

// ---------------------------------------------------------------------------
// helpers
// ---------------------------------------------------------------------------
__device__ __forceinline__ uint32_t sptr(const void* p) {
    uint32_t a;
    asm("{ .reg .u64 t; cvta.to.shared.u64 t, %1; cvt.u32.u64 %0, t; }"
        : "=r"(a) : "l"(p));
    return a;
}
__device__ __forceinline__ uint32_t packh2(float x, float y) {
    __half2 h = __floats2half2_rn(x, y);
    return *(uint32_t*)&h;
}
#define LDM_X4(r, addr)                                                         \
    asm volatile("ldmatrix.sync.aligned.m8n8.x4.shared.b16 {%0,%1,%2,%3}, [%4];" \
        : "=r"((r)[0]), "=r"((r)[1]), "=r"((r)[2]), "=r"((r)[3]) : "r"(addr))
#define LDM_X2(r, addr)                                                         \
    asm volatile("ldmatrix.sync.aligned.m8n8.x2.shared.b16 {%0,%1}, [%2];"      \
        : "=r"((r)[0]), "=r"((r)[1]) : "r"(addr))

// m16n8k16 fp16 HMMA, f32 accumulate (sm_80+ portable path)
__device__ __forceinline__ void mma_f16(float* d, const uint32_t* a, const uint32_t* b) {
    asm volatile("mma.sync.aligned.m16n8k16.row.col.f32.f16.f16.f32 "
        "{%0,%1,%2,%3}, {%4,%5,%6,%7}, {%8,%9}, {%0,%1,%2,%3};"
        : "+f"(d[0]), "+f"(d[1]), "+f"(d[2]), "+f"(d[3])
        : "r"(a[0]), "r"(a[1]), "r"(a[2]), "r"(a[3]), "r"(b[0]), "r"(b[1]));
}

// ---------------------------------------------------------------------------
// Prep: Wq|Wk|Wv -> g_WB [n=192][k=384] fp16 (Q part pre-scaled by SCALE)
// ---------------------------------------------------------------------------
__global__ void prep_kernel(const float* __restrict__ Wq, const float* __restrict__ bq,
                            const float* __restrict__ Wk, const float* __restrict__ bk,
                            const float* __restrict__ Wv, const float* __restrict__ bv) {
    int i = blockIdx.x * 256 + threadIdx.x;
    if (i < QKV_N * CEMB) {
        int n = i / CEMB, k = i % CEMB;
        const float* W = (n < 64) ? Wq : (n < 128) ? Wk : Wv;
        float w = W[(size_t)k * HEAD + (n & 63)];
        if (n < 64) w *= SCALE;
        g_WB[i] = __float2half(w);
    }
    if (i < QKV_N) {
        const float* bb = (i < 64) ? bq : (i < 128) ? bk : bv;
        float v = bb[i & 63];
        if (i < 64) v *= SCALE;
        g_bias[i] = v;
    }
}

// ---------------------------------------------------------------------------
// Kernel 1: fused QKV projection (R11 best-known version).
//   grid = (2, 1024): x = N-half (96 cols), y = M tile (128 rows). 256 thr.
// ---------------------------------------------------------------------------
#define SA_STR 40
#define SB_STR 56

__global__ __launch_bounds__(256)
void qkv_hmma_kernel(const float* __restrict__ x) {
    __shared__ __half sA[128 * SA_STR];
    __shared__ __half sB[96 * SB_STR];
    __shared__ float sbias[96];

    const int tid  = threadIdx.x;
    const int lane = tid & 31;
    const int wid  = tid >> 5;
    const int gid  = lane >> 2;
    const int tig  = lane & 3;
    const int nb   = blockIdx.x * 96;
    const int m0   = blockIdx.y * 128;
    const int wm   = (wid >> 1) * 32;
    const int wn   = (wid & 1) * 48;

    if (tid < 96) sbias[tid] = g_bias[nb + tid];

    float acc[2][6][4];
    #pragma unroll
    for (int ma = 0; ma < 2; ++ma)
        #pragma unroll
        for (int na = 0; na < 6; ++na)
            #pragma unroll
            for (int j = 0; j < 4; ++j) acc[ma][na][j] = 0.f;

    float4 pa[4];
    uint4  pb0, pb1;
    const int arow = tid >> 3, ak4 = (tid & 7) * 4;
    const int bn0 = tid >> 2, bs0 = (tid & 3) * 8;
    const int bn1 = (tid + 256) >> 2, bs1 = (tid & 3) * 8;

    #pragma unroll
    for (int it = 0; it < 4; ++it)
        pa[it] = *(const float4*)(x + (size_t)(m0 + arow + it * 32) * CEMB + ak4);
    pb0 = *(const uint4*)(g_WB + (size_t)(nb + bn0) * CEMB + bs0);
    if (tid < 128) pb1 = *(const uint4*)(g_WB + (size_t)(nb + bn1) * CEMB + bs1);

    for (int c = 0; c < NKCHUNK; ++c) {
        #pragma unroll
        for (int it = 0; it < 4; ++it) {
            uint2 s;
            s.x = packh2(pa[it].x, pa[it].y);
            s.y = packh2(pa[it].z, pa[it].w);
            *(uint2*)&sA[(arow + it * 32) * SA_STR + ak4] = s;
        }
        *(uint4*)&sB[bn0 * SB_STR + bs0] = pb0;
        if (tid < 128) *(uint4*)&sB[bn1 * SB_STR + bs1] = pb1;
        __syncthreads();

        if (c + 1 < NKCHUNK) {
            const int kb = (c + 1) * KC;
            #pragma unroll
            for (int it = 0; it < 4; ++it)
                pa[it] = *(const float4*)(x + (size_t)(m0 + arow + it * 32) * CEMB + kb + ak4);
            pb0 = *(const uint4*)(g_WB + (size_t)(nb + bn0) * CEMB + kb + bs0);
            if (tid < 128) pb1 = *(const uint4*)(g_WB + (size_t)(nb + bn1) * CEMB + kb + bs1);
        }

        #pragma unroll
        for (int ks = 0; ks < 2; ++ks) {
            const int k0 = ks * 16;
            uint32_t a[2][4];
            #pragma unroll
            for (int ma = 0; ma < 2; ++ma) {
                uint32_t ad = sptr(&sA[(wm + ma * 16 + (lane & 15)) * SA_STR
                                       + k0 + ((lane >> 4) & 1) * 8]);
                LDM_X4(a[ma], ad);
            }
            #pragma unroll
            for (int na = 0; na < 6; ++na) {
                uint32_t b2[2];
                uint32_t bd = sptr(&sB[(wn + na * 8 + (lane & 7)) * SB_STR
                                       + k0 + ((lane >> 3) & 1) * 8]);
                LDM_X2(b2, bd);
                mma_f16(acc[0][na], a[0], b2);
                mma_f16(acc[1][na], a[1], b2);
            }
        }
        __syncthreads();
    }

    #pragma unroll
    for (int ma = 0; ma < 2; ++ma) {
        int r  = m0 + wm + ma * 16 + gid;
        int bb = r >> 8;
        int sq = r & 255;
        #pragma unroll
        for (int na = 0; na < 6; ++na) {
            int lc = wn + na * 8 + 2 * tig;
            int cg = nb + lc;
            float v0 = acc[ma][na][0] + sbias[lc];
            float v1 = acc[ma][na][1] + sbias[lc + 1];
            float v2 = acc[ma][na][2] + sbias[lc];
            float v3 = acc[ma][na][3] + sbias[lc + 1];
            if (cg < 128) {
                *(__half2*)(g_QK + (size_t)r * 128 + cg)       = __floats2half2_rn(v0, v1);
                *(__half2*)(g_QK + (size_t)(r + 8) * 128 + cg) = __floats2half2_rn(v2, v3);
            } else {
                __half* vt = g_VT + ((size_t)bb * HEAD + (cg - 128)) * SEQ + sq;
                vt[0]       = __float2half(v0);
                vt[SEQ]     = __float2half(v1);
                vt[8]       = __float2half(v2);
                vt[SEQ + 8] = __float2half(v3);
            }
        }
    }
}

// ---------------------------------------------------------------------------
// Kernel 2: FlashAttention-2 style causal attention, fp16 m16n8k16.
//   grid (4, 512), 128 threads (4 warps x 16 query rows, full 64-key width).
//   Online softmax in registers; P reused as A-fragment from C-fragments.
//   SMEM: sK h[64][72] (K tile, also Q staging), sV h[64][72] (V^T tile).
// ---------------------------------------------------------------------------
#define AT_STR 72

__global__ __launch_bounds__(128)
void attn_kernel(float* __restrict__ outp) {
    __shared__ __half sK[64 * AT_STR];
    __shared__ __half sV[64 * AT_STR];

    const int tid  = threadIdx.x;
    const int lane = tid & 31;
    const int wid  = tid >> 5;       // 0..3
    const int gid  = lane >> 2;
    const int tig  = lane & 3;
    const int wm   = wid * 16;       // warp query rows [wm, wm+16)
    const int b    = blockIdx.y;
    const int qt   = blockIdx.x;
    const int r0   = qt * 64;

    const __half* Qg  = g_QK + ((size_t)b * SEQ + r0) * 128;
    const __half* Kg  = g_QK + (size_t)b * SEQ * 128 + 64;
    const __half* VTg = g_VT + (size_t)b * HEAD * SEQ;

    // Stage Q through sK, ldmatrix to registers (held whole kernel)
    #pragma unroll
    for (int it = 0; it < 4; ++it) {
        int idx = tid + it * 128;
        int q = idx >> 3, seg = (idx & 7) * 8;
        *(uint4*)&sK[q * AT_STR + seg] = *(const uint4*)(Qg + (size_t)q * 128 + seg);
    }
    __syncthreads();
    uint32_t qf[4][4];
    #pragma unroll
    for (int kc = 0; kc < 4; ++kc) {
        uint32_t ad = sptr(&sK[(wm + (lane & 15)) * AT_STR + kc * 16 + ((lane >> 4) & 1) * 8]);
        LDM_X4(qf[kc], ad);
    }

    // Prefetch kt = 0 tiles (K natural [s][h->64..128), V^T [h][s])
    uint4 kpre[4], vpre[4];
    #pragma unroll
    for (int it = 0; it < 4; ++it) {
        int idx = tid + it * 128;
        int r = idx >> 3, seg = (idx & 7) * 8;
        kpre[it] = *(const uint4*)(Kg + (size_t)r * 128 + seg);
        vpre[it] = *(const uint4*)(VTg + (size_t)r * SEQ + seg);
    }
    __syncthreads();   // Q reads done; sK reusable

    float m0 = -1e30f, m1 = -1e30f, l0 = 0.f, l1 = 0.f;
    float accO[8][4];
    #pragma unroll
    for (int na = 0; na < 8; ++na)
        #pragma unroll
        for (int j = 0; j < 4; ++j) accO[na][j] = 0.f;

    for (int kt = 0; kt <= qt; ++kt) {
        // store prefetched tiles
        #pragma unroll
        for (int it = 0; it < 4; ++it) {
            int idx = tid + it * 128;
            int r = idx >> 3, seg = (idx & 7) * 8;
            *(uint4*)&sK[r * AT_STR + seg] = kpre[it];
            *(uint4*)&sV[r * AT_STR + seg] = vpre[it];
        }
        __syncthreads();

        // prefetch next tile (overlaps compute)
        if (kt < qt) {
            #pragma unroll
            for (int it = 0; it < 4; ++it) {
                int idx = tid + it * 128;
                int r = idx >> 3, seg = (idx & 7) * 8;
                kpre[it] = *(const uint4*)(Kg + (size_t)((kt + 1) * 64 + r) * 128 + seg);
                vpre[it] = *(const uint4*)(VTg + (size_t)r * SEQ + (kt + 1) * 64 + seg);
            }
        }

        // ---- S = Q K^T : 16 x 64 in C fragments ----
        float s[8][4];
        #pragma unroll
        for (int na = 0; na < 8; ++na)
            #pragma unroll
            for (int j = 0; j < 4; ++j) s[na][j] = 0.f;

        #pragma unroll
        for (int kc = 0; kc < 4; ++kc) {
            #pragma unroll
            for (int g = 0; g < 4; ++g) {
                uint32_t kb[4];
                uint32_t bd = sptr(&sK[(g * 16 + (lane & 15)) * AT_STR
                                       + kc * 16 + ((lane >> 4) & 1) * 8]);
                LDM_X4(kb, bd);
                uint32_t b2a[2] = { kb[0], kb[2] };
                uint32_t b2b[2] = { kb[1], kb[3] };
                mma_f16(s[2 * g],     qf[kc], b2a);
                mma_f16(s[2 * g + 1], qf[kc], b2b);
            }
        }

        // ---- causal mask (diagonal tile only) ----
        if (kt == qt) {
            int q0g = r0 + wm + gid;
            #pragma unroll
            for (int na = 0; na < 8; ++na) {
                int key = kt * 64 + na * 8 + 2 * tig;
                if (key     > q0g)     s[na][0] = -1e30f;
                if (key + 1 > q0g)     s[na][1] = -1e30f;
                if (key     > q0g + 8) s[na][2] = -1e30f;
                if (key + 1 > q0g + 8) s[na][3] = -1e30f;
            }
        }

        // ---- online softmax (rows gid and gid+8) ----
        float mx0 = -1e30f, mx1 = -1e30f;
        #pragma unroll
        for (int na = 0; na < 8; ++na) {
            mx0 = fmaxf(mx0, fmaxf(s[na][0], s[na][1]));
            mx1 = fmaxf(mx1, fmaxf(s[na][2], s[na][3]));
        }
        mx0 = fmaxf(mx0, __shfl_xor_sync(0xffffffffu, mx0, 1));
        mx0 = fmaxf(mx0, __shfl_xor_sync(0xffffffffu, mx0, 2));
        mx1 = fmaxf(mx1, __shfl_xor_sync(0xffffffffu, mx1, 1));
        mx1 = fmaxf(mx1, __shfl_xor_sync(0xffffffffu, mx1, 2));
        float mn0 = fmaxf(m0, mx0), mn1 = fmaxf(m1, mx1);
        float sc0 = __expf(m0 - mn0), sc1 = __expf(m1 - mn1);
        m0 = mn0; m1 = mn1;

        float rs0 = 0.f, rs1 = 0.f;
        #pragma unroll
        for (int na = 0; na < 8; ++na) {
            s[na][0] = __expf(s[na][0] - mn0);
            s[na][1] = __expf(s[na][1] - mn0);
            s[na][2] = __expf(s[na][2] - mn1);
            s[na][3] = __expf(s[na][3] - mn1);
            rs0 += s[na][0] + s[na][1];
            rs1 += s[na][2] + s[na][3];
        }
        rs0 += __shfl_xor_sync(0xffffffffu, rs0, 1);
        rs0 += __shfl_xor_sync(0xffffffffu, rs0, 2);
        rs1 += __shfl_xor_sync(0xffffffffu, rs1, 1);
        rs1 += __shfl_xor_sync(0xffffffffu, rs1, 2);
        l0 = l0 * sc0 + rs0;
        l1 = l1 * sc1 + rs1;

        #pragma unroll
        for (int na = 0; na < 8; ++na) {
            accO[na][0] *= sc0; accO[na][1] *= sc0;
            accO[na][2] *= sc1; accO[na][3] *= sc1;
        }

        // ---- O += P V : P's C-frags reinterpreted as A-frags ----
        #pragma unroll
        for (int kc = 0; kc < 4; ++kc) {
            uint32_t pa[4] = {
                packh2(s[2 * kc][0],     s[2 * kc][1]),
                packh2(s[2 * kc][2],     s[2 * kc][3]),
                packh2(s[2 * kc + 1][0], s[2 * kc + 1][1]),
                packh2(s[2 * kc + 1][2], s[2 * kc + 1][3])
            };
            #pragma unroll
            for (int g = 0; g < 4; ++g) {
                uint32_t vb[4];
                uint32_t bd = sptr(&sV[(g * 16 + (lane & 15)) * AT_STR
                                       + kc * 16 + ((lane >> 4) & 1) * 8]);
                LDM_X4(vb, bd);
                uint32_t b2a[2] = { vb[0], vb[2] };
                uint32_t b2b[2] = { vb[1], vb[3] };
                mma_f16(accO[2 * g],     pa, b2a);
                mma_f16(accO[2 * g + 1], pa, b2b);
            }
        }
        __syncthreads();   // compute done before next tile store
    }

    // ---- epilogue: normalize, store f32 ----
    float inv0 = 1.0f / l0;
    float inv1 = 1.0f / l1;
    size_t row0 = (size_t)b * SEQ + r0 + wm + gid;
    #pragma unroll
    for (int na = 0; na < 8; ++na) {
        int c = na * 8 + 2 * tig;
        *(float2*)(outp + row0 * HEAD + c) =
            make_float2(accO[na][0] * inv0, accO[na][1] * inv0);
        *(float2*)(outp + (row0 + 8) * HEAD + c) =
            make_float2(accO[na][2] * inv1, accO[na][3] * inv1);
    }
}

// ---------------------------------------------------------------------------
extern "C" void kernel_launch(void* const* d_in, const int* in_sizes, int n_in,
                              void* d_out, int out_size) {
    const float* x  = (const float*)d_in[0];
    const float* Wq = (const float*)d_in[1];
    const float* bq = (const float*)d_in[2];
    const float* Wk = (const float*)d_in[3];
    const float* bk = (const float*)d_in[4];
    const float* Wv = (const float*)d_in[5];
    const float* bv = (const float*)d_in[6];
    float* out = (float*)d_out;

    prep_kernel<<<(QKV_N * CEMB + 255) / 256, 256>>>(Wq, bq, Wk, bk, Wv, bv);

    qkv_hmma_kernel<<<dim3(2, (BATCH * SEQ) / 128), 256>>>(x);

    attn_kernel<<<dim3(4, BATCH), 128>>>(out);
}